// round 11
// baseline (speedup 1.0000x reference)
#include <cuda_runtime.h>
#include <cstdint>

#define NB   32    // num 4x4 blocks
#define BS   4
#define DIM  128   // NB*BS
#define NREL 16    // edge relations (blocks[16] = self-loop)

// ---------------------------------------------------------------------------
// Self-loop kernel: grid-stride, warp-per-node, lane b = block b.
// W (relation 16) register-resident, loaded once per warp.
// Also initializes d_out (poisoned). mask is bool serialized as int32.
// ---------------------------------------------------------------------------
__global__ __launch_bounds__(256) void self_kernel(
    const float* __restrict__ x,
    const int*   __restrict__ mask,
    const float* __restrict__ blocks,
    float* __restrict__ out,
    int n_nodes)
{
    const int lane = threadIdx.x & 31;
    const int warp = (blockIdx.x * blockDim.x + threadIdx.x) >> 5;
    const int nw   = (gridDim.x * blockDim.x) >> 5;

    const float4* Wp = (const float4*)blocks + ((size_t)NREL * NB + lane) * 4;
    const float4 w0 = __ldg(Wp + 0);
    const float4 w1 = __ldg(Wp + 1);
    const float4 w2 = __ldg(Wp + 2);
    const float4 w3 = __ldg(Wp + 3);

    for (int n = warp; n < n_nodes; n += nw) {
        float4 o = make_float4(0.f, 0.f, 0.f, 0.f);
        if (__ldg(mask + n) != 0) {
            float4 xi = __ldg((const float4*)(x + (size_t)n * DIM) + lane);
            o.x = xi.x * w0.x + xi.y * w1.x + xi.z * w2.x + xi.w * w3.x;
            o.y = xi.x * w0.y + xi.y * w1.y + xi.z * w2.y + xi.w * w3.y;
            o.z = xi.x * w0.z + xi.y * w1.z + xi.z * w2.z + xi.w * w3.z;
            o.w = xi.x * w0.w + xi.y * w1.w + xi.z * w2.w + xi.w * w3.w;
        }
        *((float4*)(out + (size_t)n * DIM) + lane) = o;
    }
}

// ---------------------------------------------------------------------------
// Edge kernel: relation-specialized CTAs (blockIdx.y = relation g),
// register-resident W, 64-edge chunks, pairwise (2-wide) edge pipelining:
// both gathers issued before either GEMV/RED to double memory-level
// parallelism on the exposed L2 latency.
// ---------------------------------------------------------------------------
#define EDGE_THREADS 256
#define EDGE_G       56    // 56*16 = 896 CTAs (~6/SM)

__global__ __launch_bounds__(EDGE_THREADS) void edge_kernel(
    const float* __restrict__ x,
    const int*   __restrict__ src,
    const int*   __restrict__ tgt,
    const int*   __restrict__ et,
    const float* __restrict__ ew,
    const float* __restrict__ blocks,
    float* __restrict__ out,
    int n_edges)
{
    const int g    = blockIdx.y;
    const int lane = threadIdx.x & 31;

    // Register-resident W for relation g, block = lane
    const float4* Wp = (const float4*)blocks + ((size_t)g * NB + lane) * 4;
    const float4 w0 = __ldg(Wp + 0);
    const float4 w1 = __ldg(Wp + 1);
    const float4 w2 = __ldg(Wp + 2);
    const float4 w3 = __ldg(Wp + 3);

    const int warp = (blockIdx.x * EDGE_THREADS + threadIdx.x) >> 5;
    const int nw   = (gridDim.x * EDGE_THREADS) >> 5;
    const int E2   = 2 * n_edges;
    const int nch  = (E2 + 63) >> 6;       // 64-edge chunks

    for (int c = warp; c < nch; c += nw) {
        const int base = c << 6;

        // ---- subchunk A: directed edges [base, base+32) ----
        int dA = base + lane;
        bool vA = (dA < E2);
        bool fA = (dA < n_edges);
        int  eA = fA ? dA : dA - n_edges;
        int  rA = vA ? __ldg(et + eA) : -1;

        // ---- subchunk B: directed edges [base+32, base+64) ----
        int dB = base + 32 + lane;
        bool vB = (dB < E2);
        bool fB = (dB < n_edges);
        int  eB = fB ? dB : dB - n_edges;
        int  rB = vB ? __ldg(et + eB) : -1;

        unsigned mA = __ballot_sync(0xffffffffu, rA == g);
        unsigned mB = __ballot_sync(0xffffffffu, rB == g);
        unsigned long long M = ((unsigned long long)mB << 32) | mA;
        if (M == 0ull) continue;

        // matching lanes fetch packed metadata
        int   stA = 0, stB = 0;
        float wA = 0.f, wB = 0.f;
        if (rA == g) {
            int s = __ldg(fA ? src + eA : tgt + eA);
            int t = __ldg(fA ? tgt + eA : src + eA);
            stA = s | (t << 16);
            wA  = __ldg(ew + eA);
        }
        if (rB == g) {
            int s = __ldg(fB ? src + eB : tgt + eB);
            int t = __ldg(fB ? tgt + eB : src + eB);
            stB = s | (t << 16);
            wB  = __ldg(ew + eB);
        }

        while (M) {
            const int k0 = __ffsll(M) - 1;
            M &= M - 1;
            int k1 = -1;
            if (M) { k1 = __ffsll(M) - 1; M &= M - 1; }
            const int k1s = (k1 >= 0) ? k1 : k0;

            // broadcast (k uniform across warp; both shfls full-warp)
            const int   l0 = k0 & 31, l1 = k1s & 31;
            const int   stA0 = __shfl_sync(0xffffffffu, stA, l0);
            const int   stB0 = __shfl_sync(0xffffffffu, stB, l0);
            const float wA0  = __shfl_sync(0xffffffffu, wA,  l0);
            const float wB0  = __shfl_sync(0xffffffffu, wB,  l0);
            const int   stA1 = __shfl_sync(0xffffffffu, stA, l1);
            const int   stB1 = __shfl_sync(0xffffffffu, stB, l1);
            const float wA1  = __shfl_sync(0xffffffffu, wA,  l1);
            const float wB1  = __shfl_sync(0xffffffffu, wB,  l1);

            const int   st0 = (k0 < 32) ? stA0 : stB0;
            const float we0 = (k0 < 32) ? wA0  : wB0;
            const int   st1 = (k1s < 32) ? stA1 : stB1;
            const float we1 = (k1s < 32) ? wA1  : wB1;

            const int s0 = st0 & 0xFFFF, t0 = st0 >> 16;
            const int s1 = st1 & 0xFFFF, t1 = st1 >> 16;

            // both gathers in flight before any use
            float4 xa = __ldg((const float4*)(x + (size_t)s0 * DIM) + lane);
            float4 xb = __ldg((const float4*)(x + (size_t)s1 * DIM) + lane);

            float4 oa;
            oa.x = (xa.x * w0.x + xa.y * w1.x + xa.z * w2.x + xa.w * w3.x) * we0;
            oa.y = (xa.x * w0.y + xa.y * w1.y + xa.z * w2.y + xa.w * w3.y) * we0;
            oa.z = (xa.x * w0.z + xa.y * w1.z + xa.z * w2.z + xa.w * w3.z) * we0;
            oa.w = (xa.x * w0.w + xa.y * w1.w + xa.z * w2.w + xa.w * w3.w) * we0;
            float* dst0 = out + (size_t)t0 * DIM + lane * 4;
            asm volatile("red.global.add.v4.f32 [%0], {%1, %2, %3, %4};"
                         :: "l"(dst0), "f"(oa.x), "f"(oa.y), "f"(oa.z), "f"(oa.w));

            if (k1 >= 0) {
                float4 ob;
                ob.x = (xb.x * w0.x + xb.y * w1.x + xb.z * w2.x + xb.w * w3.x) * we1;
                ob.y = (xb.x * w0.y + xb.y * w1.y + xb.z * w2.y + xb.w * w3.y) * we1;
                ob.z = (xb.x * w0.z + xb.y * w1.z + xb.z * w2.z + xb.w * w3.z) * we1;
                ob.w = (xb.x * w0.w + xb.y * w1.w + xb.z * w2.w + xb.w * w3.w) * we1;
                float* dst1 = out + (size_t)t1 * DIM + lane * 4;
                asm volatile("red.global.add.v4.f32 [%0], {%1, %2, %3, %4};"
                             :: "l"(dst1), "f"(ob.x), "f"(ob.y), "f"(ob.z), "f"(ob.w));
            }
        }
    }
}

// ---------------------------------------------------------------------------
// Inputs (metadata order):
//   0: x              float32 (10000*128)
//   1: node_keep_mask int32   (10000)
//   2: source         int32   (160000)
//   3: target         int32   (160000)
//   4: edge_type      int32   (160000)
//   5: edge_weights   float32 (160000)
//   6: blocks         float32 (17*32*4*4)
// Output: float32 (10000*128)
// ---------------------------------------------------------------------------
extern "C" void kernel_launch(void* const* d_in, const int* in_sizes, int n_in,
                              void* d_out, int out_size)
{
    const float* x      = (const float*)d_in[0];
    const int*   mask   = (const int*)d_in[1];
    const int*   src    = (const int*)d_in[2];
    const int*   tgt    = (const int*)d_in[3];
    const int*   et     = (const int*)d_in[4];
    const float* ew     = (const float*)d_in[5];
    const float* blocks = (const float*)d_in[6];
    float*       out    = (float*)d_out;

    const int n_nodes = in_sizes[1];
    const int n_edges = in_sizes[2];

    // 1) Self-loop + out init
    self_kernel<<<296, 256>>>(x, mask, blocks, out, n_nodes);

    // 2) Relation-specialized edge messages
    dim3 grid(EDGE_G, NREL);
    edge_kernel<<<grid, EDGE_THREADS>>>(x, src, tgt, et, ew, blocks, out, n_edges);
}

// round 12
// speedup vs baseline: 1.0716x; 1.0716x over previous
#include <cuda_runtime.h>
#include <cstdint>

#define NB   32    // num 4x4 blocks
#define BS   4
#define DIM  128   // NB*BS
#define NREL 16    // edge relations (blocks[16] = self-loop)

// ---------------------------------------------------------------------------
// Self-loop kernel: grid-stride, warp-per-node, lane b = block b.
// W (relation 16) register-resident, loaded once per warp.
// Also initializes d_out (poisoned). mask is bool serialized as int32.
// ---------------------------------------------------------------------------
__global__ __launch_bounds__(256) void self_kernel(
    const float* __restrict__ x,
    const int*   __restrict__ mask,
    const float* __restrict__ blocks,
    float* __restrict__ out,
    int n_nodes)
{
    const int lane = threadIdx.x & 31;
    const int warp = (blockIdx.x * blockDim.x + threadIdx.x) >> 5;
    const int nw   = (gridDim.x * blockDim.x) >> 5;

    const float4* Wp = (const float4*)blocks + ((size_t)NREL * NB + lane) * 4;
    const float4 w0 = __ldg(Wp + 0);
    const float4 w1 = __ldg(Wp + 1);
    const float4 w2 = __ldg(Wp + 2);
    const float4 w3 = __ldg(Wp + 3);

    for (int n = warp; n < n_nodes; n += nw) {
        float4 o = make_float4(0.f, 0.f, 0.f, 0.f);
        if (__ldg(mask + n) != 0) {
            float4 xi = __ldg((const float4*)(x + (size_t)n * DIM) + lane);
            o.x = xi.x * w0.x + xi.y * w1.x + xi.z * w2.x + xi.w * w3.x;
            o.y = xi.x * w0.y + xi.y * w1.y + xi.z * w2.y + xi.w * w3.y;
            o.z = xi.x * w0.z + xi.y * w1.z + xi.z * w2.z + xi.w * w3.z;
            o.w = xi.x * w0.w + xi.y * w1.w + xi.z * w2.w + xi.w * w3.w;
        }
        *((float4*)(out + (size_t)n * DIM) + lane) = o;
    }
}

// ---------------------------------------------------------------------------
// Edge kernel: relation-specialized CTAs (blockIdx.y = relation g),
// register-resident W. 32-edge chunks; ballot for et==g; matched metadata
// packed to s|(t<<16) so broadcasting an edge costs 2 shfls. Matched edges
// processed PAIRWISE: both x[src] gathers issued before either GEMV/RED
// (2x MLP on the exposed L2 latency) at the same shfl cost as serial.
// ---------------------------------------------------------------------------
#define EDGE_THREADS 256
#define EDGE_G       74    // 74*16 = 1184 CTAs

__global__ __launch_bounds__(EDGE_THREADS) void edge_kernel(
    const float* __restrict__ x,
    const int*   __restrict__ src,
    const int*   __restrict__ tgt,
    const int*   __restrict__ et,
    const float* __restrict__ ew,
    const float* __restrict__ blocks,
    float* __restrict__ out,
    int n_edges)
{
    const int g    = blockIdx.y;
    const int lane = threadIdx.x & 31;

    // Register-resident W for relation g, block = lane
    const float4* Wp = (const float4*)blocks + ((size_t)g * NB + lane) * 4;
    const float4 w0 = __ldg(Wp + 0);
    const float4 w1 = __ldg(Wp + 1);
    const float4 w2 = __ldg(Wp + 2);
    const float4 w3 = __ldg(Wp + 3);

    const int warp = (blockIdx.x * EDGE_THREADS + threadIdx.x) >> 5;
    const int nw   = (gridDim.x * EDGE_THREADS) >> 5;
    const int E2   = 2 * n_edges;
    const int nch  = (E2 + 31) >> 5;

    for (int c = warp; c < nch; c += nw) {
        const int d     = (c << 5) + lane;
        const bool valid = (d < E2);
        const bool fwd   = (d < n_edges);
        const int  e     = fwd ? d : d - n_edges;

        int r = -1;
        if (valid) r = __ldg(et + e);

        unsigned m = __ballot_sync(0xffffffffu, r == g);
        if (m == 0u) continue;

        // matching lanes fetch packed metadata
        int   st_l = 0;
        float w_l  = 0.f;
        if (r == g) {
            int s = __ldg(fwd ? src + e : tgt + e);
            int t = __ldg(fwd ? tgt + e : src + e);
            st_l = s | (t << 16);
            w_l  = __ldg(ew + e);
        }

        while (m) {
            const int k0 = __ffs(m) - 1;
            m &= m - 1;
            int k1 = -1;
            if (m) { k1 = __ffs(m) - 1; m &= m - 1; }
            const int k1s = (k1 >= 0) ? k1 : k0;

            const int   st0 = __shfl_sync(0xffffffffu, st_l, k0);
            const float we0 = __shfl_sync(0xffffffffu, w_l,  k0);
            const int   st1 = __shfl_sync(0xffffffffu, st_l, k1s);
            const float we1 = __shfl_sync(0xffffffffu, w_l,  k1s);

            const int s0 = st0 & 0xFFFF, t0 = st0 >> 16;
            const int s1 = st1 & 0xFFFF, t1 = st1 >> 16;

            // both gathers in flight before any use
            float4 xa = __ldg((const float4*)(x + (size_t)s0 * DIM) + lane);
            float4 xb = __ldg((const float4*)(x + (size_t)s1 * DIM) + lane);

            float4 oa;
            oa.x = (xa.x * w0.x + xa.y * w1.x + xa.z * w2.x + xa.w * w3.x) * we0;
            oa.y = (xa.x * w0.y + xa.y * w1.y + xa.z * w2.y + xa.w * w3.y) * we0;
            oa.z = (xa.x * w0.z + xa.y * w1.z + xa.z * w2.z + xa.w * w3.z) * we0;
            oa.w = (xa.x * w0.w + xa.y * w1.w + xa.z * w2.w + xa.w * w3.w) * we0;
            float* dst0 = out + (size_t)t0 * DIM + lane * 4;
            asm volatile("red.global.add.v4.f32 [%0], {%1, %2, %3, %4};"
                         :: "l"(dst0), "f"(oa.x), "f"(oa.y), "f"(oa.z), "f"(oa.w));

            if (k1 >= 0) {
                float4 ob;
                ob.x = (xb.x * w0.x + xb.y * w1.x + xb.z * w2.x + xb.w * w3.x) * we1;
                ob.y = (xb.x * w0.y + xb.y * w1.y + xb.z * w2.y + xb.w * w3.y) * we1;
                ob.z = (xb.x * w0.z + xb.y * w1.z + xb.z * w2.z + xb.w * w3.z) * we1;
                ob.w = (xb.x * w0.w + xb.y * w1.w + xb.z * w2.w + xb.w * w3.w) * we1;
                float* dst1 = out + (size_t)t1 * DIM + lane * 4;
                asm volatile("red.global.add.v4.f32 [%0], {%1, %2, %3, %4};"
                             :: "l"(dst1), "f"(ob.x), "f"(ob.y), "f"(ob.z), "f"(ob.w));
            }
        }
    }
}

// ---------------------------------------------------------------------------
// Inputs (metadata order):
//   0: x              float32 (10000*128)
//   1: node_keep_mask int32   (10000)
//   2: source         int32   (160000)
//   3: target         int32   (160000)
//   4: edge_type      int32   (160000)
//   5: edge_weights   float32 (160000)
//   6: blocks         float32 (17*32*4*4)
// Output: float32 (10000*128)
// ---------------------------------------------------------------------------
extern "C" void kernel_launch(void* const* d_in, const int* in_sizes, int n_in,
                              void* d_out, int out_size)
{
    const float* x      = (const float*)d_in[0];
    const int*   mask   = (const int*)d_in[1];
    const int*   src    = (const int*)d_in[2];
    const int*   tgt    = (const int*)d_in[3];
    const int*   et     = (const int*)d_in[4];
    const float* ew     = (const float*)d_in[5];
    const float* blocks = (const float*)d_in[6];
    float*       out    = (float*)d_out;

    const int n_nodes = in_sizes[1];
    const int n_edges = in_sizes[2];

    // 1) Self-loop + out init
    self_kernel<<<296, 256>>>(x, mask, blocks, out, n_nodes);

    // 2) Relation-specialized edge messages
    dim3 grid(EDGE_G, NREL);
    edge_kernel<<<grid, EDGE_THREADS>>>(x, src, tgt, et, ew, blocks, out, n_edges);
}